// round 11
// baseline (speedup 1.0000x reference)
#include <cuda_runtime.h>

#define Bn 256
#define Sn 64
#define Dn 64
#define Fn 10
#define NCn 10
#define Pf 2016.0f
#define NT 256
#define INVP (1.0f / 2018.0f)

// global scratch for U, V  (256 batches x 64 rows x 16 float4)
__device__ float4 g_U[Bn * Sn * 16];
__device__ float4 g_V[Bn * Sn * 16];

// ---------------- K1 smem layout (floats) ----------------
#define K1_E     0        // 32 x 64
#define K1_W     2048     // 64 x 192 weight panel [W1a|W1b|fw1]; FH aliased here after GEMM
#define K1_FH    2048     // 32 x 64 (alias)
#define K1_FW1L  14336    // 64
#define K1_CC    14400    // 10 x 64
#define K1_FW2T  15040    // 10 x 64
#define K1_FR    15680    // 32
#define K1_SID   15712    // 32 (int)
#define K1_DIST  15744    // 32 x 10
#define K1_FLOATS 16064   // 64,256 B -> 3 CTAs/SM

__global__ __launch_bounds__(NT, 3)
void k1_rows(const int* __restrict__ ids, const float* __restrict__ table,
             const float* __restrict__ cw1, const float* __restrict__ cb1,
             const float* __restrict__ fw1, const float* __restrict__ fb1,
             const float* __restrict__ fw2g, const float* __restrict__ fb2,
             const float* __restrict__ ccg, const float* __restrict__ catf,
             const float* __restrict__ tot, float* __restrict__ out) {
    extern __shared__ float sm[];
    const int t = threadIdx.x;
    const int h = blockIdx.x;          // row half
    const int b = blockIdx.y;
    const int dblk = t & 15;           // float4 col 0..15
    const int sp   = t >> 4;           // 0..15
    const int s0   = sp * 2;           // 2 local rows per thread

    // ---- stage: ids/freq (own 32 rows), weight panel, cc, fw2T ----
    if (t < 32) {
        int id = ids[b * Sn + h * 32 + t];
        ((int*)(sm + K1_SID))[t] = id;
        sm[K1_FR + t] = catf[id] / tot[0];
    }
    {
        float4* Wp = (float4*)(sm + K1_W);          // [64][48] float4
        const float4* cw14 = (const float4*)cw1;    // [128][16]
        const float4* fw14 = (const float4*)fw1;    // [65][16]
#pragma unroll
        for (int u = 0; u < 12; ++u) {
            int i = t + NT * u;                     // 0..3071
            int r = i / 48, c = i - r * 48;
            float4 v;
            if (c < 16)       v = cw14[r * 16 + c];
            else if (c < 32)  v = cw14[(64 + r) * 16 + (c - 16)];
            else              v = fw14[r * 16 + (c - 32)];
            Wp[i] = v;
        }
        if (t < 16)  ((float4*)(sm + K1_FW1L))[t] = fw14[64 * 16 + t];
        if (t < 160) ((float4*)(sm + K1_CC))[t]   = ((const float4*)ccg)[t];
        for (int i = t; i < Dn * Fn; i += NT) {     // fw2T[f*64+d]
            int f = i >> 6, d = i & 63;
            sm[K1_FW2T + i] = fw2g[d * Fn + f];
        }
    }
    __syncthreads();

    // ---- gather own 32 E rows ----
    {
        float4* E4 = (float4*)(sm + K1_E);
        const float4* T4 = (const float4*)table;
        const int* sid = (const int*)(sm + K1_SID);
#pragma unroll
        for (int c = 0; c < 2; ++c) {
            int lin = t + NT * c;                   // 0..511
            int s = lin >> 4, q = lin & 15;
            E4[lin] = T4[sid[s] * 16 + q];
        }
    }
    __syncthreads();

    // ---- fused GEMM: [U|V|FHpre](32x192) = E32 @ panel ----
    float acc[3][2][4];
#pragma unroll
    for (int g = 0; g < 3; ++g)
#pragma unroll
        for (int si = 0; si < 2; ++si)
#pragma unroll
            for (int c = 0; c < 4; ++c) acc[g][si][c] = 0.f;
    {
        const float4* E4 = (const float4*)(sm + K1_E);
        const float4* W4 = (const float4*)(sm + K1_W);
        for (int kk = 0; kk < 16; ++kk) {
            float4 e0 = E4[(s0 + 0) * 16 + kk];
            float4 e1 = E4[(s0 + 1) * 16 + kk];
#pragma unroll
            for (int r = 0; r < 4; ++r) {
                float a0 = r == 0 ? e0.x : r == 1 ? e0.y : r == 2 ? e0.z : e0.w;
                float a1 = r == 0 ? e1.x : r == 1 ? e1.y : r == 2 ? e1.z : e1.w;
#pragma unroll
                for (int g = 0; g < 3; ++g) {
                    float4 w = W4[(4 * kk + r) * 48 + g * 16 + dblk];
                    acc[g][0][0] += a0 * w.x; acc[g][0][1] += a0 * w.y;
                    acc[g][0][2] += a0 * w.z; acc[g][0][3] += a0 * w.w;
                    acc[g][1][0] += a1 * w.x; acc[g][1][1] += a1 * w.y;
                    acc[g][1][2] += a1 * w.z; acc[g][1][3] += a1 * w.w;
                }
            }
        }
    }
    __syncthreads();    // panel reads done -> FH alias safe

    // ---- writeback: U,V -> global scratch ; FH -> smem ----
    {
        float4 bv  = ((const float4*)cb1)[dblk];
        float4 fbv = ((const float4*)fb1)[dblk];
        float4 wl  = ((const float4*)(sm + K1_FW1L))[dblk];
        float4* FH4 = (float4*)(sm + K1_FH);
#pragma unroll
        for (int si = 0; si < 2; ++si) {
            int gs = h * 32 + s0 + si;              // global row
            float4 u = {acc[0][si][0] + bv.x, acc[0][si][1] + bv.y,
                        acc[0][si][2] + bv.z, acc[0][si][3] + bv.w};
            g_U[b * 1024 + gs * 16 + dblk] = u;
            float4 v = {acc[1][si][0], acc[1][si][1], acc[1][si][2], acc[1][si][3]};
            g_V[b * 1024 + gs * 16 + dblk] = v;
            float fq = sm[K1_FR + s0 + si];
            float4 fh;
            fh.x = fmaxf(acc[2][si][0] + fq * wl.x + fbv.x, 0.f);
            fh.y = fmaxf(acc[2][si][1] + fq * wl.y + fbv.y, 0.f);
            fh.z = fmaxf(acc[2][si][2] + fq * wl.z + fbv.z, 0.f);
            fh.w = fmaxf(acc[2][si][3] + fq * wl.w + fbv.w, 0.f);
            FH4[(s0 + si) * 16 + dblk] = fh;
        }
    }

    // ---- distances for own 32 rows (320 items) ----
    {
        const float4* E4 = (const float4*)(sm + K1_E);
        const float4* C4 = (const float4*)(sm + K1_CC);
        for (int it = t; it < 32 * NCn; it += NT) {
            int s = it / (unsigned)NCn, c = it - s * NCn;
            float dot = 0.f, e2 = 0.f, c2 = 0.f;
#pragma unroll 4
            for (int kk = 0; kk < 16; ++kk) {
                float4 e = E4[s * 16 + kk];
                float4 cv = C4[c * 16 + kk];
                dot += e.x * cv.x + e.y * cv.y + e.z * cv.z + e.w * cv.w;
                e2  += e.x * e.x + e.y * e.y + e.z * e.z + e.w * e.w;
                c2  += cv.x * cv.x + cv.y * cv.y + cv.z * cv.z + cv.w * cv.w;
            }
            sm[K1_DIST + it] = sqrtf(fmaxf(e2 + c2 - 2.f * dot, 0.f));
        }
    }
    __syncthreads();

    // ---- softmax per own token ----
    if (t < 32) {
        float* dr = sm + K1_DIST + t * NCn;
        float mn = dr[0];
#pragma unroll
        for (int c = 1; c < NCn; ++c) mn = fminf(mn, dr[c]);
        float e[NCn]; float ssum = 0.f;
#pragma unroll
        for (int c = 0; c < NCn; ++c) { e[c] = __expf(mn - dr[c]); ssum += e[c]; }
        float inv = 1.f / ssum;
#pragma unroll
        for (int c = 0; c < NCn; ++c) dr[c] = e[c] * inv;
    }
    __syncthreads();

    // ---- freq dot + partial output: out = (ff + fb2 + dist)*invP ----
    {
        const float4* FH4 = (const float4*)(sm + K1_FH);
        const float4* W2T = (const float4*)(sm + K1_FW2T);
        for (int it = t; it < 32 * Fn; it += NT) {
            int s = it / (unsigned)Fn, f = it - s * Fn;
            float ff = 0.f;
#pragma unroll 4
            for (int kk = 0; kk < 16; ++kk) {
                float4 hh = FH4[s * 16 + kk];
                float4 w  = W2T[f * 16 + kk];
                ff += hh.x * w.x + hh.y * w.y + hh.z * w.z + hh.w * w.w;
            }
            out[b * (Sn * Fn) + (h * 32 + s) * Fn + f] =
                (ff + fb2[f] + sm[K1_DIST + it]) * INVP;
        }
    }
}

// ---------------- K2 smem layout (floats) ----------------
#define K2_V    0        // 64 x 64
#define K2_HP   4096     // 16 x 64
#define K2_HS   5120     // 64
#define K2_CW2  5184     // 64 x 10
#define K2_CS   5824     // 16
#define K2_FLOATS 5840

__global__ __launch_bounds__(NT, 2)
void k2_pairs(const float* __restrict__ cw2g, const float* __restrict__ cb2,
              float* __restrict__ out) {
    extern __shared__ float sm[];
    const int t = threadIdx.x;
    const int b = blockIdx.x;
    const int dblk = t & 15;
    const int sp   = t >> 4;     // 0..15

    // stage V + cw2
    {
        float4* V4 = (float4*)(sm + K2_V);
        const float4* gv = g_V + b * 1024;
#pragma unroll
        for (int c = 0; c < 4; ++c) V4[t + NT * c] = gv[t + NT * c];
        if (t < 160) ((float4*)(sm + K2_CW2))[t] = ((const float4*)cw2g)[t];
    }
    __syncthreads();

    // balanced pair sum: thread owns i in {sp, 63-sp, 16+sp, 47-sp} -> 126 iters
    {
        const float4* V4 = (const float4*)(sm + K2_V);
        const float4* gu = g_U + b * 1024;
        const int iset[4] = {sp, 63 - sp, 16 + sp, 47 - sp};
        float4 a = {0.f, 0.f, 0.f, 0.f};
#pragma unroll
        for (int q = 0; q < 4; ++q) {
            int i = iset[q];
            float4 u = gu[i * 16 + dblk];
#pragma unroll 4
            for (int j = i + 1; j < Sn; ++j) {
                float4 v = V4[j * 16 + dblk];
                a.x += fmaxf(u.x + v.x, 0.f);
                a.y += fmaxf(u.y + v.y, 0.f);
                a.z += fmaxf(u.z + v.z, 0.f);
                a.w += fmaxf(u.w + v.w, 0.f);
            }
        }
        ((float4*)(sm + K2_HP))[sp * 16 + dblk] = a;
    }
    __syncthreads();

    if (t < Sn) {
        const float* Hp = sm + K2_HP;
        float s = 0.f;
#pragma unroll
        for (int g = 0; g < 16; ++g) s += Hp[g * Dn + t];
        sm[K2_HS + t] = s;
    }
    __syncthreads();

    if (t < NCn) {
        float s = 0.f;
#pragma unroll 8
        for (int d = 0; d < Dn; ++d) s += sm[K2_HS + d] * sm[K2_CW2 + d * Fn + t];
        sm[K2_CS + t] = (s + Pf * cb2[t]) * INVP;
    }
    __syncthreads();

    // out += csum (already scaled by invP)
    for (int it = t; it < Sn * Fn; it += NT) {
        int f = it % (unsigned)Fn;
        out[b * (Sn * Fn) + it] += sm[K2_CS + f];
    }
}

extern "C" void kernel_launch(void* const* d_in, const int* in_sizes, int n_in,
                              void* d_out, int out_size) {
    const int*   ids  = (const int*)d_in[0];
    const float* tab  = (const float*)d_in[1];
    const float* cw1  = (const float*)d_in[2];
    const float* cb1  = (const float*)d_in[3];
    const float* cw2  = (const float*)d_in[4];
    const float* cb2  = (const float*)d_in[5];
    const float* fw1  = (const float*)d_in[6];
    const float* fb1  = (const float*)d_in[7];
    const float* fw2  = (const float*)d_in[8];
    const float* fb2  = (const float*)d_in[9];
    const float* cc   = (const float*)d_in[10];
    const float* catf = (const float*)d_in[11];
    const float* tot  = (const float*)d_in[12];
    float* out = (float*)d_out;

    cudaFuncSetAttribute(k1_rows, cudaFuncAttributeMaxDynamicSharedMemorySize,
                         K1_FLOATS * (int)sizeof(float));
    dim3 g1(2, Bn);
    k1_rows<<<g1, NT, K1_FLOATS * sizeof(float)>>>(
        ids, tab, cw1, cb1, fw1, fb1, fw2, fb2, cc, catf, tot, out);
    k2_pairs<<<Bn, NT, K2_FLOATS * sizeof(float)>>>(cw2, cb2, out);
}

// round 13
// speedup vs baseline: 1.2267x; 1.2267x over previous
#include <cuda_runtime.h>

#define Bn 256
#define Sn 64
#define Fn 10
#define NCn 10
#define Pf 2016.0f
#define NT 384
#define INVP (1.0f / 2018.0f)

// float offsets into dynamic smem
#define OFF_E     0        // 64 x 64 embeddings
#define OFF_WU    4096     // 64 x 64 W1a  -> U after GEMM (aliased)
#define OFF_WV    8192     // 64 x 64 W1b  -> V after GEMM
#define OFF_WF    12288    // 64 x 64 fw1[:64] -> FH after GEMM
#define OFF_FW1L  16384    // 64 (fw1 row 64)
#define OFF_CW2   16448    // 64 x 10
#define OFF_FW2T  17088    // 10 x 64 transposed freq_w2
#define OFF_CC    17728    // 10 x 64
#define OFF_FR    18368    // 64
#define OFF_HP    18432    // 6 x 64 pair partials
#define OFF_HS    18816    // 64
#define OFF_CS    18880    // 16
#define OFF_DIST  18896    // 64 x 10
#define SMEM_FLOATS 19536  // 78,144 B -> 2 CTAs/SM

__global__ __launch_bounds__(NT, 2)
void cate_enc_kernel(const int* __restrict__ ids, const float* __restrict__ table,
                     const float* __restrict__ cw1, const float* __restrict__ cb1,
                     const float* __restrict__ cw2g, const float* __restrict__ cb2,
                     const float* __restrict__ fw1, const float* __restrict__ fb1,
                     const float* __restrict__ fw2g, const float* __restrict__ fb2,
                     const float* __restrict__ ccg, const float* __restrict__ catf,
                     const float* __restrict__ tot, float* __restrict__ out) {
    extern __shared__ float sm[];
    const int t = threadIdx.x;
    const int b = blockIdx.x;

    // ---------- ph0: stage everything + gather E (single barrier) ----------
    {
        float4* WU4 = (float4*)(sm + OFF_WU);
        float4* WV4 = (float4*)(sm + OFF_WV);
        float4* WF4 = (float4*)(sm + OFF_WF);
        const float4* cw14 = (const float4*)cw1;    // [128][16]
        const float4* fw14 = (const float4*)fw1;    // [65][16]
        for (int i = t; i < 1024; i += NT) {
            WU4[i] = cw14[i];
            WV4[i] = cw14[1024 + i];
            WF4[i] = fw14[i];
        }
        if (t < 16)  ((float4*)(sm + OFF_FW1L))[t] = fw14[1024 + t];
        if (t < 160) {
            ((float4*)(sm + OFF_CC))[t]  = ((const float4*)ccg)[t];
            ((float4*)(sm + OFF_CW2))[t] = ((const float4*)cw2g)[t];
        }
        for (int i = t; i < Sn * Fn; i += NT) {     // fw2T[f*64+d] = fw2[d*10+f]
            int f = i >> 6, d = i & 63;
            sm[OFF_FW2T + i] = fw2g[d * Fn + f];
        }
        if (t < Sn) {
            int id = ids[b * Sn + t];
            sm[OFF_FR + t] = catf[id] / tot[0];
        }
        float4* E4 = (float4*)(sm + OFF_E);
        const float4* T4 = (const float4*)table;
        for (int i = t; i < 1024; i += NT) {
            int s = i >> 4, q = i & 15;
            int id = ids[b * Sn + s];               // direct gmem read (L1-cached)
            E4[i] = T4[id * 16 + q];
        }
    }
    __syncthreads();

    // ---------- GEMMs: warpgroup wg in {0,1,2} computes 64x64 over its panel ----
    {
        const int wg = t >> 7;            // 0:U 1:V 2:FH
        const int wt = t & 127;
        const int dblk = wt & 15;         // float4 col 0..15
        const int sp   = wt >> 4;         // 0..7
        const int s0   = sp * 8;          // 8 rows per thread
        const float4* W4 = (const float4*)(sm + OFF_WU + wg * 4096);
        const float4* E4 = (const float4*)(sm + OFF_E);
        float4 acc[8];
#pragma unroll
        for (int m = 0; m < 8; ++m) acc[m] = make_float4(0.f, 0.f, 0.f, 0.f);

        for (int kk = 0; kk < 16; ++kk) {
            float4 w0 = W4[(4 * kk + 0) * 16 + dblk];
            float4 w1 = W4[(4 * kk + 1) * 16 + dblk];
            float4 w2 = W4[(4 * kk + 2) * 16 + dblk];
            float4 w3 = W4[(4 * kk + 3) * 16 + dblk];
#pragma unroll
            for (int hf = 0; hf < 2; ++hf) {
                float4 e0 = E4[(s0 + hf * 4 + 0) * 16 + kk];
                float4 e1 = E4[(s0 + hf * 4 + 1) * 16 + kk];
                float4 e2 = E4[(s0 + hf * 4 + 2) * 16 + kk];
                float4 e3 = E4[(s0 + hf * 4 + 3) * 16 + kk];
#pragma unroll
                for (int m = 0; m < 4; ++m) {
                    float4 e = m == 0 ? e0 : m == 1 ? e1 : m == 2 ? e2 : e3;
                    float4& a = acc[hf * 4 + m];
                    a.x += e.x * w0.x + e.y * w1.x + e.z * w2.x + e.w * w3.x;
                    a.y += e.x * w0.y + e.y * w1.y + e.z * w2.y + e.w * w3.y;
                    a.z += e.x * w0.z + e.y * w1.z + e.z * w2.z + e.w * w3.z;
                    a.w += e.x * w0.w + e.y * w1.w + e.z * w2.w + e.w * w3.w;
                }
            }
        }
        // all 128 threads of this warpgroup done reading its panel
        asm volatile("bar.sync %0, %1;" :: "r"(wg + 1), "r"(128) : "memory");
        float4* O4 = (float4*)(sm + OFF_WU + wg * 4096);
        if (wg == 0) {
            float4 bv = ((const float4*)cb1)[dblk];
#pragma unroll
            for (int m = 0; m < 8; ++m) {
                float4 o = {acc[m].x + bv.x, acc[m].y + bv.y,
                            acc[m].z + bv.z, acc[m].w + bv.w};
                O4[(s0 + m) * 16 + dblk] = o;
            }
        } else if (wg == 1) {
#pragma unroll
            for (int m = 0; m < 8; ++m) O4[(s0 + m) * 16 + dblk] = acc[m];
        } else {
            float4 fbv = ((const float4*)fb1)[dblk];
            float4 wl  = ((const float4*)(sm + OFF_FW1L))[dblk];
#pragma unroll
            for (int m = 0; m < 8; ++m) {
                float fq = sm[OFF_FR + s0 + m];
                float4 o;
                o.x = fmaxf(acc[m].x + fq * wl.x + fbv.x, 0.f);
                o.y = fmaxf(acc[m].y + fq * wl.y + fbv.y, 0.f);
                o.z = fmaxf(acc[m].z + fq * wl.z + fbv.z, 0.f);
                o.w = fmaxf(acc[m].w + fq * wl.w + fbv.w, 0.f);
                O4[(s0 + m) * 16 + dblk] = o;
            }
        }
    }
    __syncthreads();

    // ---------- pair sum (scalar-d, 6 balanced groups) + distances ----------
    {
        const int d = t & 63, g = t >> 6;          // g 0..5
        const float* U = sm + OFF_WU;
        const float* V = sm + OFF_WV;
        float a1 = 0.f, a2 = 0.f;
#pragma unroll
        for (int k = 0; k < 5; ++k) {
            int i1 = 12 * k + g, i2 = 12 * k + 11 - g;    // i1 < i2
            float u1 = U[i1 * 64 + d];
            float u2 = U[i2 * 64 + d];
#pragma unroll 4
            for (int j = i1 + 1; j <= i2; ++j)
                a1 += fmaxf(u1 + V[j * 64 + d], 0.f);
#pragma unroll 4
            for (int j = i2 + 1; j < Sn; ++j) {
                float v = V[j * 64 + d];
                a1 += fmaxf(u1 + v, 0.f);
                a2 += fmaxf(u2 + v, 0.f);
            }
        }
        if (g < 4) {                                 // remainder rows 60..63
            int i = 60 + g;
            float u = U[i * 64 + d];
            for (int j = i + 1; j < Sn; ++j)
                a1 += fmaxf(u + V[j * 64 + d], 0.f);
        }
        sm[OFF_HP + g * 64 + d] = a1 + a2;
    }
    {   // distances (640 items, fused norms)
        const float4* E4 = (const float4*)(sm + OFF_E);
        const float4* C4 = (const float4*)(sm + OFF_CC);
        for (int it = t; it < Sn * NCn; it += NT) {
            int s = it / (unsigned)NCn, c = it - s * NCn;
            float dot = 0.f, e2 = 0.f, c2 = 0.f;
#pragma unroll 4
            for (int kk = 0; kk < 16; ++kk) {
                float4 e = E4[s * 16 + kk];
                float4 cv = C4[c * 16 + kk];
                dot += e.x * cv.x + e.y * cv.y + e.z * cv.z + e.w * cv.w;
                e2  += e.x * e.x + e.y * e.y + e.z * e.z + e.w * e.w;
                c2  += cv.x * cv.x + cv.y * cv.y + cv.z * cv.z + cv.w * cv.w;
            }
            sm[OFF_DIST + it] = sqrtf(fmaxf(e2 + c2 - 2.f * dot, 0.f));
        }
    }
    __syncthreads();

    // ---------- softmax (t<64) ; Hsum (64<=t<128) ----------
    if (t < Sn) {
        float* dr = sm + OFF_DIST + t * NCn;
        float mn = dr[0];
#pragma unroll
        for (int c = 1; c < NCn; ++c) mn = fminf(mn, dr[c]);
        float e[NCn]; float ssum = 0.f;
#pragma unroll
        for (int c = 0; c < NCn; ++c) { e[c] = __expf(mn - dr[c]); ssum += e[c]; }
        float inv = 1.f / ssum;
#pragma unroll
        for (int c = 0; c < NCn; ++c) dr[c] = e[c] * inv;
    } else if (t < 2 * Sn) {
        int d = t - Sn;
        const float* Hp = sm + OFF_HP;
        float s = 0.f;
#pragma unroll
        for (int g = 0; g < 6; ++g) s += Hp[g * 64 + d];
        sm[OFF_HS + d] = s;
    }
    __syncthreads();

    // ---------- csum ----------
    if (t < NCn) {
        float s = 0.f;
#pragma unroll 8
        for (int d = 0; d < Sn; ++d) s += sm[OFF_HS + d] * sm[OFF_CW2 + d * Fn + t];
        sm[OFF_CS + t] = s + Pf * cb2[t];
    }
    __syncthreads();

    // ---------- epilogue ----------
    {
        const float4* FH4 = (const float4*)(sm + OFF_WF);
        const float4* W2T = (const float4*)(sm + OFF_FW2T);
        for (int it = t; it < Sn * Fn; it += NT) {
            int s = it / (unsigned)Fn, f = it - s * Fn;
            float ff = 0.f;
#pragma unroll 4
            for (int kk = 0; kk < 16; ++kk) {
                float4 h = FH4[s * 16 + kk];
                float4 w = W2T[f * 16 + kk];
                ff += h.x * w.x + h.y * w.y + h.z * w.z + h.w * w.w;
            }
            out[b * (Sn * Fn) + it] =
                (ff + fb2[f] + sm[OFF_CS + f] + sm[OFF_DIST + it]) * INVP;
        }
    }
}

extern "C" void kernel_launch(void* const* d_in, const int* in_sizes, int n_in,
                              void* d_out, int out_size) {
    const int*   ids  = (const int*)d_in[0];
    const float* tab  = (const float*)d_in[1];
    const float* cw1  = (const float*)d_in[2];
    const float* cb1  = (const float*)d_in[3];
    const float* cw2  = (const float*)d_in[4];
    const float* cb2  = (const float*)d_in[5];
    const float* fw1  = (const float*)d_in[6];
    const float* fb1  = (const float*)d_in[7];
    const float* fw2  = (const float*)d_in[8];
    const float* fb2  = (const float*)d_in[9];
    const float* cc   = (const float*)d_in[10];
    const float* catf = (const float*)d_in[11];
    const float* tot  = (const float*)d_in[12];
    float* out = (float*)d_out;

    cudaFuncSetAttribute(cate_enc_kernel,
                         cudaFuncAttributeMaxDynamicSharedMemorySize,
                         SMEM_FLOATS * (int)sizeof(float));
    cate_enc_kernel<<<Bn, NT, SMEM_FLOATS * sizeof(float)>>>(
        ids, tab, cw1, cb1, cw2, cb2, fw1, fb1, fw2, fb2, cc, catf, tot, out);
}

// round 14
// speedup vs baseline: 1.4691x; 1.1976x over previous
#include <cuda_runtime.h>

#define Bn 256
#define Sn 64
#define Dn 64
#define Fn 10
#define NCn 10
#define Pf 2016.0f

struct __align__(16) Smem {
    float E[Sn * Dn];       // embeddings           4096
    float U[Sn * Dn];       // E@W1a + b1, later FH 4096
    float V[Sn * Dn];       // E@W1b                4096
    float W[65 * Dn];       // staging: W1a/W1b/freq_w1
    float cw2[Dn * Fn];     // comb_w2
    float fw2[Dn * Fn];     // freq_w2
    float cc[NCn * Dn];     // cluster centers
    float fr[Sn];           // per-token frequency
    float e2s[Sn];          // |e_s|^2
    float cn2[16];          // |c|^2
    float Hpart[16 * Dn];   // partial pair sums (16 groups)
    float Hsum[Dn];
    float csum[16];         // combo_sum (incl P*b2)
    float dist[Sn * NCn];   // distances -> softmax in place
    int   sid[Sn];
};

__device__ __forceinline__ void gemm16(const float4* __restrict__ E4,
                                       const float4* __restrict__ W4,
                                       int s0, int dblk, float acc[4][4]) {
#pragma unroll
    for (int kk = 0; kk < 16; ++kk) {
        float4 w0 = W4[(4 * kk + 0) * 16 + dblk];
        float4 w1 = W4[(4 * kk + 1) * 16 + dblk];
        float4 w2 = W4[(4 * kk + 2) * 16 + dblk];
        float4 w3 = W4[(4 * kk + 3) * 16 + dblk];
#pragma unroll
        for (int si = 0; si < 4; ++si) {
            float4 e = E4[(s0 + si) * 16 + kk];
            acc[si][0] += e.x * w0.x + e.y * w1.x + e.z * w2.x + e.w * w3.x;
            acc[si][1] += e.x * w0.y + e.y * w1.y + e.z * w2.y + e.w * w3.y;
            acc[si][2] += e.x * w0.z + e.y * w1.z + e.z * w2.z + e.w * w3.z;
            acc[si][3] += e.x * w0.w + e.y * w1.w + e.z * w2.w + e.w * w3.w;
        }
    }
}

__global__ __launch_bounds__(256, 2)
void cate_enc_kernel(const int* __restrict__ ids, const float* __restrict__ table,
                     const float* __restrict__ cw1, const float* __restrict__ cb1,
                     const float* __restrict__ cw2g, const float* __restrict__ cb2,
                     const float* __restrict__ fw1, const float* __restrict__ fb1,
                     const float* __restrict__ fw2g, const float* __restrict__ fb2,
                     const float* __restrict__ ccg, const float* __restrict__ catf,
                     const float* __restrict__ tot, float* __restrict__ out) {
    extern __shared__ char smraw[];
    Smem& sm = *reinterpret_cast<Smem*>(smraw);
    const int t = threadIdx.x;
    const int b = blockIdx.x;

    // ---- phase 0a: ids + freqs, stage W1a and small weights ----
    if (t < Sn) {
        int id = ids[b * Sn + t];
        sm.sid[t] = id;
        sm.fr[t] = catf[id] / tot[0];
    }
    {
        float4* W4 = (float4*)sm.W;
        const float4* g4 = (const float4*)cw1;   // rows 0..63 = W1a
#pragma unroll
        for (int c = 0; c < 4; ++c) W4[t + 256 * c] = g4[t + 256 * c];
        if (t < 160) {
            ((float4*)sm.cw2)[t] = ((const float4*)cw2g)[t];
            ((float4*)sm.fw2)[t] = ((const float4*)fw2g)[t];
            ((float4*)sm.cc)[t]  = ((const float4*)ccg)[t];
        }
    }
    __syncthreads();

    // ---- phase 0b: embedding gather (float4, 16 per row) ----
    {
        float4* E4 = (float4*)sm.E;
        const float4* T4 = (const float4*)table;
#pragma unroll
        for (int c = 0; c < 4; ++c) {
            int lin = t + 256 * c;
            int s = lin >> 4, q = lin & 15;
            E4[lin] = T4[sm.sid[s] * 16 + q];
        }
    }
    __syncthreads();

    const int sblk = t >> 4, dblk = t & 15;
    const int s0 = sblk * 4;

    // ---- phase 1: U = E @ W1a + b1 ----
    {
        float acc[4][4] = {};
        gemm16((const float4*)sm.E, (const float4*)sm.W, s0, dblk, acc);
        float4 bv = ((const float4*)cb1)[dblk];
        float4* U4 = (float4*)sm.U;
#pragma unroll
        for (int si = 0; si < 4; ++si) {
            float4 o;
            o.x = acc[si][0] + bv.x; o.y = acc[si][1] + bv.y;
            o.z = acc[si][2] + bv.z; o.w = acc[si][3] + bv.w;
            U4[(s0 + si) * 16 + dblk] = o;
        }
    }
    __syncthreads();

    // ---- phase 2: stage W1b ----
    {
        float4* W4 = (float4*)sm.W;
        const float4* g4 = (const float4*)cw1;
#pragma unroll
        for (int c = 0; c < 4; ++c) W4[t + 256 * c] = g4[1024 + t + 256 * c];
    }
    __syncthreads();

    // ---- phase 3: V = E @ W1b ----
    {
        float acc[4][4] = {};
        gemm16((const float4*)sm.E, (const float4*)sm.W, s0, dblk, acc);
        float4* V4 = (float4*)sm.V;
#pragma unroll
        for (int si = 0; si < 4; ++si) {
            float4 o;
            o.x = acc[si][0]; o.y = acc[si][1]; o.z = acc[si][2]; o.w = acc[si][3];
            V4[(s0 + si) * 16 + dblk] = o;
        }
    }
    __syncthreads();

    // ---- phase 4: stage freq_w1 (65 rows); balanced float4 pair sum overlaps ----
    {
        float4* W4 = (float4*)sm.W;
        const float4* g4 = (const float4*)fw1;
#pragma unroll
        for (int c = 0; c < 4; ++c) W4[t + 256 * c] = g4[t + 256 * c];
        if (t < 16) W4[1024 + t] = g4[1024 + t];
    }
    {   // thread (g, c) owns i in {g, 31-g, 32+g, 63-g} -> exactly 126 iters
        const float4* U4 = (const float4*)sm.U;
        const float4* V4 = (const float4*)sm.V;
        const int g = t >> 4, c = t & 15;
        const int iset[4] = {g, 31 - g, 32 + g, 63 - g};
        float4 a = {0.f, 0.f, 0.f, 0.f};
#pragma unroll
        for (int q = 0; q < 4; ++q) {
            int i = iset[q];
            float4 u = U4[i * 16 + c];
#pragma unroll 4
            for (int j = i + 1; j < Sn; ++j) {
                float4 v = V4[j * 16 + c];
                a.x += fmaxf(u.x + v.x, 0.f);
                a.y += fmaxf(u.y + v.y, 0.f);
                a.z += fmaxf(u.z + v.z, 0.f);
                a.w += fmaxf(u.w + v.w, 0.f);
            }
        }
        ((float4*)sm.Hpart)[g * 16 + c] = a;
    }
    __syncthreads();

    // ---- phase 5: reduce Hsum (16 partials), |e|^2, |c|^2 ----
    if (t < Sn) {
        float s = 0.f;
#pragma unroll
        for (int g = 0; g < 16; ++g) s += sm.Hpart[g * Dn + t];
        sm.Hsum[t] = s;
        const float4* E4 = (const float4*)sm.E;
        float s2 = 0.f;
#pragma unroll
        for (int kk = 0; kk < 16; ++kk) {
            float4 e = E4[t * 16 + kk];
            s2 += e.x * e.x + e.y * e.y + e.z * e.z + e.w * e.w;
        }
        sm.e2s[t] = s2;
    } else if (t < Sn + NCn) {
        int c = t - Sn;
        const float4* C4 = (const float4*)sm.cc;
        float s2 = 0.f;
#pragma unroll
        for (int kk = 0; kk < 16; ++kk) {
            float4 e = C4[c * 16 + kk];
            s2 += e.x * e.x + e.y * e.y + e.z * e.z + e.w * e.w;
        }
        sm.cn2[c] = s2;
    }
    __syncthreads();

    // ---- phase 6: FH = relu(E@fw1[:64] + fr*fw1[64] + fb1) -> U; distances; csum ----
    {
        float acc[4][4] = {};
        gemm16((const float4*)sm.E, (const float4*)sm.W, s0, dblk, acc);
        float4 fbv = ((const float4*)fb1)[dblk];
        float4 wl  = ((const float4*)(sm.W + 64 * Dn))[dblk];
        float4* U4 = (float4*)sm.U;
#pragma unroll
        for (int si = 0; si < 4; ++si) {
            float fq = sm.fr[s0 + si];
            float4 o;
            o.x = fmaxf(acc[si][0] + fq * wl.x + fbv.x, 0.f);
            o.y = fmaxf(acc[si][1] + fq * wl.y + fbv.y, 0.f);
            o.z = fmaxf(acc[si][2] + fq * wl.z + fbv.z, 0.f);
            o.w = fmaxf(acc[si][3] + fq * wl.w + fbv.w, 0.f);
            U4[(s0 + si) * 16 + dblk] = o;
        }
    }
    {
        const int s = t & 63, g = t >> 6;
        const float4* E4 = (const float4*)sm.E;
        const float4* C4 = (const float4*)sm.cc;
        for (int c = g; c < NCn; c += 4) {
            float dot = 0.f;
#pragma unroll
            for (int kk = 0; kk < 16; ++kk) {
                float4 e = E4[s * 16 + kk];
                float4 cv = C4[c * 16 + kk];
                dot += e.x * cv.x + e.y * cv.y + e.z * cv.z + e.w * cv.w;
            }
            float d2 = sm.e2s[s] + sm.cn2[c] - 2.f * dot;
            sm.dist[s * NCn + c] = sqrtf(fmaxf(d2, 0.f));
        }
    }
    if (t < NCn) {
        float s = 0.f;
#pragma unroll 8
        for (int d = 0; d < Dn; ++d) s += sm.Hsum[d] * sm.cw2[d * Fn + t];
        sm.csum[t] = s + Pf * cb2[t];
    }
    __syncthreads();

    // ---- phase 7: softmax(-dist) per token ----
    if (t < Sn) {
        float mn = sm.dist[t * NCn];
#pragma unroll
        for (int c = 1; c < NCn; ++c) mn = fminf(mn, sm.dist[t * NCn + c]);
        float e[NCn]; float ssum = 0.f;
#pragma unroll
        for (int c = 0; c < NCn; ++c) { e[c] = __expf(mn - sm.dist[t * NCn + c]); ssum += e[c]; }
        float inv = 1.f / ssum;
#pragma unroll
        for (int c = 0; c < NCn; ++c) sm.dist[t * NCn + c] = e[c] * inv;
    }
    __syncthreads();

    // ---- phase 8: final output ----
    const float invP = 1.f / (Pf + 2.f);
    for (int lin = t; lin < Sn * Fn; lin += 256) {
        int s = lin / Fn, f = lin - s * Fn;
        float ff = 0.f;
#pragma unroll 8
        for (int d = 0; d < Dn; ++d) ff += sm.U[s * Dn + d] * sm.fw2[d * Fn + f];
        out[b * (Sn * Fn) + lin] = (ff + fb2[f] + sm.csum[f] + sm.dist[lin]) * invP;
    }
}

extern "C" void kernel_launch(void* const* d_in, const int* in_sizes, int n_in,
                              void* d_out, int out_size) {
    const int*   ids  = (const int*)d_in[0];
    const float* tab  = (const float*)d_in[1];
    const float* cw1  = (const float*)d_in[2];
    const float* cb1  = (const float*)d_in[3];
    const float* cw2  = (const float*)d_in[4];
    const float* cb2  = (const float*)d_in[5];
    const float* fw1  = (const float*)d_in[6];
    const float* fb1  = (const float*)d_in[7];
    const float* fw2  = (const float*)d_in[8];
    const float* fb2  = (const float*)d_in[9];
    const float* cc   = (const float*)d_in[10];
    const float* catf = (const float*)d_in[11];
    const float* tot  = (const float*)d_in[12];
    float* out = (float*)d_out;

    cudaFuncSetAttribute(cate_enc_kernel,
                         cudaFuncAttributeMaxDynamicSharedMemorySize,
                         (int)sizeof(Smem));
    cate_enc_kernel<<<Bn, 256, sizeof(Smem)>>>(ids, tab, cw1, cb1, cw2, cb2,
                                               fw1, fb1, fw2, fb2, cc, catf,
                                               tot, out);
}